// round 5
// baseline (speedup 1.0000x reference)
#include <cuda_runtime.h>

#define M_PTS   200000
#define NCAM    6
#define C_IMG   96
#define H_FEAT  32
#define W_FEAT  88
#define PTS_DIM 128
#define FUSE_DIM 224
#define GZ 32
#define GY 512
#define GX 448
#define GRID_N (GZ*GY*GX)
#define TILES 3125              // ceil(M/64), M divisible by 64

// ---- static scratch (no runtime allocation allowed) ----
__device__ float g_xf[12 + NCAM*24];                 // Rinv(9), t(3), per cam: L3(9),lt(3),A3(9),at(3)
__device__ float g_imgt[NCAM*H_FEAT*W_FEAT*C_IMG];   // NHWC transposed image feats
__device__ int   g_grid[GRID_N];
__device__ float g_fuse[(size_t)M_PTS*FUSE_DIM];
__device__ int   g_cnt[27];
__device__ int2  g_ents[27*(size_t)M_PTS];           // (dst i, src j) per offset bucket
__device__ float g_acc[(size_t)M_PTS*PTS_DIM];

// ---------------- setup: fold transforms ----------------
__global__ void k_setup(const float* __restrict__ laug,
                        const float* __restrict__ l2i,
                        const float* __restrict__ iaug) {
    if (threadIdx.x != 0 || blockIdx.x != 0) return;
    float R[9], t[3];
    for (int i = 0; i < 3; i++) {
        for (int j = 0; j < 3; j++) R[i*3+j] = laug[i*4+j];
        t[i] = laug[i*4+3];
    }
    float a=R[0],b=R[1],c=R[2],d=R[3],e=R[4],f=R[5],g=R[6],h=R[7],i9=R[8];
    float A_ = e*i9 - f*h;
    float B_ = f*g - d*i9;
    float C_ = d*h - e*g;
    float det = a*A_ + b*B_ + c*C_;
    float inv[9] = {
        A_/det,        (c*h - b*i9)/det, (b*f - c*e)/det,
        B_/det,        (a*i9 - c*g)/det, (c*d - a*f)/det,
        C_/det,        (b*g - a*h)/det,  (a*e - b*d)/det };
    for (int k = 0; k < 9; k++) g_xf[k] = inv[k];
    for (int k = 0; k < 3; k++) g_xf[9+k] = t[k];
    for (int n = 0; n < NCAM; n++) {
        float* X = g_xf + 12 + n*24;
        for (int i = 0; i < 3; i++) {
            for (int j = 0; j < 3; j++) {
                X[i*3+j]      = l2i[n*16 + i*4 + j];   // L3
                X[12 + i*3+j] = iaug[n*16 + i*4 + j];  // A3
            }
            X[9+i]  = l2i[n*16 + i*4 + 3];             // lt
            X[21+i] = iaug[n*16 + i*4 + 3];            // at
        }
    }
}

// ---------------- NCHW -> NHWC transpose ----------------
__global__ void k_transpose(const float* __restrict__ img) {
    int i = blockIdx.x*blockDim.x + threadIdx.x;
    const int total = NCAM*C_IMG*H_FEAT*W_FEAT;
    if (i >= total) return;
    int c = i % C_IMG;
    int w = (i / C_IMG) % W_FEAT;
    int h = (i / (C_IMG*W_FEAT)) % H_FEAT;
    int n = i / (C_IMG*W_FEAT*H_FEAT);
    g_imgt[i] = img[((n*C_IMG + c)*H_FEAT + h)*W_FEAT + w];
}

// ---------------- init grid/-1, counters, acc ----------------
__global__ void k_init() {
    int i = blockIdx.x*blockDim.x + threadIdx.x;
    if (i < GRID_N) g_grid[i] = -1;
    if (i < M_PTS*PTS_DIM) g_acc[i] = 0.0f;
    if (i < 27) g_cnt[i] = 0;
}

// ---------------- scatter voxel index (last-write-wins == max idx) ----------------
__global__ void k_scatter(const int* __restrict__ vc) {
    int m = blockIdx.x*blockDim.x + threadIdx.x;
    if (m >= M_PTS) return;
    int cz = vc[4*m+1], cy = vc[4*m+2], cx = vc[4*m+3];
    atomicMax(&g_grid[(cz*GY + cy)*GX + cx], m);
}

// ---------------- project + bilinear sample + build fuse ----------------
__global__ __launch_bounds__(256) void k_fuse(const float* __restrict__ pts,
                                              const int* __restrict__ vc) {
    int warp = (blockIdx.x*blockDim.x + threadIdx.x) >> 5;
    int lane = threadIdx.x & 31;
    if (warp >= M_PTS) return;
    int m = warp;
    int cz = vc[4*m+1], cy = vc[4*m+2], cx = vc[4*m+3];
    float cfx = (float)cx, cfy = (float)cy, cfz = (float)cz;

    float p0 = cfx - g_xf[9], p1 = cfy - g_xf[10], p2 = cfz - g_xf[11];
    float q0 = g_xf[0]*p0 + g_xf[1]*p1 + g_xf[2]*p2;
    float q1 = g_xf[3]*p0 + g_xf[4]*p1 + g_xf[5]*p2;
    float q2 = g_xf[6]*p0 + g_xf[7]*p1 + g_xf[8]*p2;

    float acc0 = 0.f, acc1 = 0.f, acc2 = 0.f;

    #pragma unroll 1
    for (int n = 0; n < NCAM; n++) {
        const float* X = g_xf + 12 + n*24;
        float c0 = X[0]*q0 + X[1]*q1 + X[2]*q2 + X[9];
        float c1 = X[3]*q0 + X[4]*q1 + X[5]*q2 + X[10];
        float c2 = X[6]*q0 + X[7]*q1 + X[8]*q2 + X[11];
        float z  = fminf(fmaxf(c2, 1e-5f), 1e5f);
        float vx = c0 / z, vy = c1 / z;
        float d0 = X[12]*vx + X[13]*vy + X[14]*z + X[21];
        float d1 = X[15]*vx + X[16]*vy + X[17]*z + X[22];
        float gx = (d0 / 704.0f - 0.5f) * 2.0f;
        float gy = (d1 / 256.0f - 0.5f) * 2.0f;
        float x = (gx + 1.0f) * 0.5f * (float)(W_FEAT - 1);
        float y = (gy + 1.0f) * 0.5f * (float)(H_FEAT - 1);
        float x0f = floorf(x), y0f = floorf(y);
        float wx1 = x - x0f, wy1 = y - y0f;
        float wx0 = 1.0f - wx1, wy0 = 1.0f - wy1;
        bool vx0 = (x0f >= 0.f) && (x0f <= (float)(W_FEAT-1));
        bool vx1 = (x0f+1.f >= 0.f) && (x0f+1.f <= (float)(W_FEAT-1));
        bool vy0 = (y0f >= 0.f) && (y0f <= (float)(H_FEAT-1));
        bool vy1 = (y0f+1.f >= 0.f) && (y0f+1.f <= (float)(H_FEAT-1));
        float w00 = (vx0 && vy0) ? wx0*wy0 : 0.f;
        float w10 = (vx1 && vy0) ? wx1*wy0 : 0.f;
        float w01 = (vx0 && vy1) ? wx0*wy1 : 0.f;
        float w11 = (vx1 && vy1) ? wx1*wy1 : 0.f;
        if (w00 == 0.f && w10 == 0.f && w01 == 0.f && w11 == 0.f) continue;

        int x0i = (int)fminf(fmaxf(x0f,      0.f), (float)(W_FEAT-1));
        int x1i = (int)fminf(fmaxf(x0f+1.f,  0.f), (float)(W_FEAT-1));
        int y0i = (int)fminf(fmaxf(y0f,      0.f), (float)(H_FEAT-1));
        int y1i = (int)fminf(fmaxf(y0f+1.f,  0.f), (float)(H_FEAT-1));

        const float* row0 = g_imgt + ((size_t)(n*H_FEAT + y0i)*W_FEAT)*C_IMG;
        const float* row1 = g_imgt + ((size_t)(n*H_FEAT + y1i)*W_FEAT)*C_IMG;
        const float* p00 = row0 + x0i*C_IMG;
        const float* p10 = row0 + x1i*C_IMG;
        const float* p01 = row1 + x0i*C_IMG;
        const float* p11 = row1 + x1i*C_IMG;

        acc0 += w00*p00[lane]    + w10*p10[lane]    + w01*p01[lane]    + w11*p11[lane];
        acc1 += w00*p00[lane+32] + w10*p10[lane+32] + w01*p01[lane+32] + w11*p11[lane+32];
        acc2 += w00*p00[lane+64] + w10*p10[lane+64] + w01*p01[lane+64] + w11*p11[lane+64];
    }

    float* frow = g_fuse + (size_t)m*FUSE_DIM;
    float4 pv = ((const float4*)(pts + (size_t)m*PTS_DIM))[lane];
    ((float4*)frow)[lane] = pv;
    frow[128 + lane] = acc0;
    frow[160 + lane] = acc1;
    frow[192 + lane] = acc2;
}

// ---------------- build per-offset worklists ----------------
__global__ void k_entries(const int* __restrict__ vc) {
    int m = blockIdx.x*blockDim.x + threadIdx.x;
    bool inb = m < M_PTS;
    int cz = 0, cy = 0, cx = 0;
    if (inb) { cz = vc[4*m+1]; cy = vc[4*m+2]; cx = vc[4*m+3]; }
    int lane = threadIdx.x & 31;
    #pragma unroll 1
    for (int k = 0; k < 27; k++) {
        int dz = k/9 - 1, dy = (k%9)/3 - 1, dx = k%3 - 1;
        int nz = cz + dz, ny = cy + dy, nx = cx + dx;
        int nid = -1;
        if (inb && nz >= 0 && nz < GZ && ny >= 0 && ny < GY && nx >= 0 && nx < GX)
            nid = g_grid[(nz*GY + ny)*GX + nx];
        bool has = nid >= 0;
        unsigned mask = __ballot_sync(0xffffffffu, has);
        if (mask) {
            int leader = __ffs(mask) - 1;
            int base = 0;
            if (lane == leader) base = atomicAdd(&g_cnt[k], __popc(mask));
            base = __shfl_sync(0xffffffffu, base, leader);
            if (has) {
                int pos = base + __popc(mask & ((1u << lane) - 1u));
                g_ents[(size_t)k*M_PTS + pos] = make_int2(m, nid);
            }
        }
    }
}

// ---------------- compacted gather-GEMM-scatter (fp32) ----------------
__global__ __launch_bounds__(256) void k_conv(const float* __restrict__ conv_w) {
    int k    = blockIdx.x / TILES;
    int tile = blockIdx.x % TILES;
    int n = g_cnt[k];
    int e0 = tile * 64;
    if (e0 >= n) return;

    __shared__ int2  se[64];
    __shared__ float As[16][64];
    __shared__ float Bs[16][128];

    int tid = threadIdx.x;
    if (tid < 64) {
        int e = e0 + tid;
        se[tid] = (e < n) ? g_ents[(size_t)k*M_PTS + e] : make_int2(-1, -1);
    }
    __syncthreads();

    const float* Wk = conv_w + (size_t)k*FUSE_DIM*PTS_DIM;
    int ty = tid >> 4, tx = tid & 15;          // 16x16 thread grid; 4 rows x 8 cols each
    int ar = tid >> 2, aq = tid & 3;           // A loader: row 0..63, quad 0..3
    int aj = se[ar].y;
    const float4* arow = (const float4*)(g_fuse + (size_t)(aj >= 0 ? aj : 0)*FUSE_DIM);

    float acc[4][8];
    #pragma unroll
    for (int r = 0; r < 4; r++)
        #pragma unroll
        for (int c = 0; c < 8; c++) acc[r][c] = 0.f;

    for (int k0 = 0; k0 < FUSE_DIM; k0 += 16) {
        float4 av = make_float4(0.f, 0.f, 0.f, 0.f);
        if (aj >= 0) av = arow[(k0 >> 2) + aq];
        As[aq*4+0][ar] = av.x;
        As[aq*4+1][ar] = av.y;
        As[aq*4+2][ar] = av.z;
        As[aq*4+3][ar] = av.w;

        const float4* brow = (const float4*)(Wk + (size_t)(k0 + ty)*PTS_DIM);
        float4 b0 = brow[tx*2], b1 = brow[tx*2 + 1];
        *((float4*)&Bs[ty][tx*8])     = b0;
        *((float4*)&Bs[ty][tx*8 + 4]) = b1;
        __syncthreads();

        #pragma unroll
        for (int kk = 0; kk < 16; kk++) {
            float4 a = *((const float4*)&As[kk][ty*4]);
            float4 bb0 = *((const float4*)&Bs[kk][tx*8]);
            float4 bb1 = *((const float4*)&Bs[kk][tx*8 + 4]);
            float av4[4] = {a.x, a.y, a.z, a.w};
            float bv[8]  = {bb0.x, bb0.y, bb0.z, bb0.w, bb1.x, bb1.y, bb1.z, bb1.w};
            #pragma unroll
            for (int r = 0; r < 4; r++)
                #pragma unroll
                for (int c = 0; c < 8; c++)
                    acc[r][c] = fmaf(av4[r], bv[c], acc[r][c]);
        }
        __syncthreads();
    }

    #pragma unroll
    for (int r = 0; r < 4; r++) {
        int i = se[ty*4 + r].x;
        if (i >= 0) {
            float* dst = g_acc + (size_t)i*PTS_DIM + tx*8;
            #pragma unroll
            for (int c = 0; c < 8; c++) atomicAdd(&dst[c], acc[r][c]);
        }
    }
}

// ---------------- BN + ReLU epilogue ----------------
__global__ void k_bn(const float* __restrict__ gamma, const float* __restrict__ beta,
                     const float* __restrict__ mean,  const float* __restrict__ var,
                     float* __restrict__ out) {
    int i = blockIdx.x*blockDim.x + threadIdx.x;     // over float4 elements
    if (i >= M_PTS*PTS_DIM/4) return;
    int c4 = (i & 31) * 4;
    float4 v = ((const float4*)g_acc)[i];
    float4 o;
    {
        float s = rsqrtf(var[c4+0] + 1e-5f);
        o.x = fmaxf((v.x - mean[c4+0]) * s * gamma[c4+0] + beta[c4+0], 0.f);
    }
    {
        float s = rsqrtf(var[c4+1] + 1e-5f);
        o.y = fmaxf((v.y - mean[c4+1]) * s * gamma[c4+1] + beta[c4+1], 0.f);
    }
    {
        float s = rsqrtf(var[c4+2] + 1e-5f);
        o.z = fmaxf((v.z - mean[c4+2]) * s * gamma[c4+2] + beta[c4+2], 0.f);
    }
    {
        float s = rsqrtf(var[c4+3] + 1e-5f);
        o.w = fmaxf((v.w - mean[c4+3]) * s * gamma[c4+3] + beta[c4+3], 0.f);
    }
    ((float4*)out)[i] = o;
}

extern "C" void kernel_launch(void* const* d_in, const int* in_sizes, int n_in,
                              void* d_out, int out_size) {
    const float* pts   = (const float*)d_in[0];
    const int*   vc    = (const int*)  d_in[1];
    const float* img   = (const float*)d_in[2];
    const float* l2i   = (const float*)d_in[3];
    const float* iaug  = (const float*)d_in[4];
    const float* laug  = (const float*)d_in[5];
    const float* convw = (const float*)d_in[6];
    const float* gamma = (const float*)d_in[7];
    const float* beta  = (const float*)d_in[8];
    const float* mean  = (const float*)d_in[9];
    const float* var   = (const float*)d_in[10];
    float* out = (float*)d_out;

    k_setup<<<1, 32>>>(laug, l2i, iaug);
    {
        const int total = NCAM*C_IMG*H_FEAT*W_FEAT;
        k_transpose<<<(total + 255)/256, 256>>>(img);
    }
    k_init<<<(M_PTS*PTS_DIM + 255)/256, 256>>>();
    k_scatter<<<(M_PTS + 255)/256, 256>>>(vc);
    k_fuse<<<M_PTS/8, 256>>>(pts, vc);
    k_entries<<<(M_PTS + 255)/256, 256>>>(vc);
    k_conv<<<27*TILES, 256>>>(convw);
    k_bn<<<(M_PTS*PTS_DIM/4 + 255)/256, 256>>>(gamma, beta, mean, var, out);
}

// round 8
// speedup vs baseline: 1.3242x; 1.3242x over previous
#include <cuda_runtime.h>

#define M_PTS   200000
#define NCAM    6
#define C_IMG   96
#define H_FEAT  32
#define W_FEAT  88
#define PTS_DIM 128
#define FUSE_DIM 224
#define GZ 32
#define GY 512
#define GX 448
#define GRID_N (GZ*GY*GX)
#define TILE_E 128
#define CENTER_TILES ((M_PTS + TILE_E - 1) / TILE_E)   // 1563

typedef unsigned long long ull;

// ---- static scratch (no runtime allocation allowed) ----
__device__ float g_xf[12 + NCAM*24];                 // Rinv(9), t(3), per cam: L3(9),lt(3),A3(9),at(3)
__device__ float g_imgt[NCAM*H_FEAT*W_FEAT*C_IMG];   // NHWC transposed image feats
__device__ int   g_grid[GRID_N];
__device__ float g_fuse[(size_t)M_PTS*FUSE_DIM];
__device__ int   g_cnt[27];
__device__ int   g_tileoff[28];
__device__ int2  g_ents[27*(size_t)M_PTS];           // (dst i, src j) per offset bucket
__device__ float g_acc[(size_t)M_PTS*PTS_DIM];

__device__ __forceinline__ ull pack2(float v) {
    ull r; asm("mov.b64 %0, {%1, %1};" : "=l"(r) : "f"(v)); return r;
}
__device__ __forceinline__ void ffma2(ull &d, ull a, ull b) {
    asm("fma.rn.f32x2 %0, %1, %2, %0;" : "+l"(d) : "l"(a), "l"(b));
}
__device__ __forceinline__ float lo32(ull v) { return __uint_as_float((unsigned)(v & 0xffffffffull)); }
__device__ __forceinline__ float hi32(ull v) { return __uint_as_float((unsigned)(v >> 32)); }

// ---------------- setup: fold transforms ----------------
__global__ void k_setup(const float* __restrict__ laug,
                        const float* __restrict__ l2i,
                        const float* __restrict__ iaug) {
    if (threadIdx.x != 0 || blockIdx.x != 0) return;
    float R[9], t[3];
    for (int i = 0; i < 3; i++) {
        for (int j = 0; j < 3; j++) R[i*3+j] = laug[i*4+j];
        t[i] = laug[i*4+3];
    }
    float a=R[0],b=R[1],c=R[2],d=R[3],e=R[4],f=R[5],g=R[6],h=R[7],i9=R[8];
    float A_ = e*i9 - f*h;
    float B_ = f*g - d*i9;
    float C_ = d*h - e*g;
    float det = a*A_ + b*B_ + c*C_;
    float inv[9] = {
        A_/det,        (c*h - b*i9)/det, (b*f - c*e)/det,
        B_/det,        (a*i9 - c*g)/det, (c*d - a*f)/det,
        C_/det,        (b*g - a*h)/det,  (a*e - b*d)/det };
    for (int k = 0; k < 9; k++) g_xf[k] = inv[k];
    for (int k = 0; k < 3; k++) g_xf[9+k] = t[k];
    for (int n = 0; n < NCAM; n++) {
        float* X = g_xf + 12 + n*24;
        for (int i = 0; i < 3; i++) {
            for (int j = 0; j < 3; j++) {
                X[i*3+j]      = l2i[n*16 + i*4 + j];   // L3
                X[12 + i*3+j] = iaug[n*16 + i*4 + j];  // A3
            }
            X[9+i]  = l2i[n*16 + i*4 + 3];             // lt
            X[21+i] = iaug[n*16 + i*4 + 3];            // at
        }
    }
}

// ---------------- NCHW -> NHWC transpose ----------------
__global__ void k_transpose(const float* __restrict__ img) {
    int i = blockIdx.x*blockDim.x + threadIdx.x;
    const int total = NCAM*C_IMG*H_FEAT*W_FEAT;
    if (i >= total) return;
    int c = i % C_IMG;
    int w = (i / C_IMG) % W_FEAT;
    int h = (i / (C_IMG*W_FEAT)) % H_FEAT;
    int n = i / (C_IMG*W_FEAT*H_FEAT);
    g_imgt[i] = img[((n*C_IMG + c)*H_FEAT + h)*W_FEAT + w];
}

// ---------------- init grid/-1, counters ----------------
__global__ void k_init() {
    int i = blockIdx.x*blockDim.x + threadIdx.x;
    if (i < GRID_N) g_grid[i] = -1;
    if (i < 27) g_cnt[i] = 0;
}

// ---------------- scatter voxel index (last-write-wins == max idx) ----------------
__global__ void k_scatter(const int* __restrict__ vc) {
    int m = blockIdx.x*blockDim.x + threadIdx.x;
    if (m >= M_PTS) return;
    int cz = vc[4*m+1], cy = vc[4*m+2], cx = vc[4*m+3];
    atomicMax(&g_grid[(cz*GY + cy)*GX + cx], m);
}

// ---------------- project + bilinear sample + build fuse ----------------
__global__ __launch_bounds__(256) void k_fuse(const float* __restrict__ pts,
                                              const int* __restrict__ vc) {
    int warp = (blockIdx.x*blockDim.x + threadIdx.x) >> 5;
    int lane = threadIdx.x & 31;
    if (warp >= M_PTS) return;
    int m = warp;
    int cz = vc[4*m+1], cy = vc[4*m+2], cx = vc[4*m+3];
    float cfx = (float)cx, cfy = (float)cy, cfz = (float)cz;

    float p0 = cfx - g_xf[9], p1 = cfy - g_xf[10], p2 = cfz - g_xf[11];
    float q0 = g_xf[0]*p0 + g_xf[1]*p1 + g_xf[2]*p2;
    float q1 = g_xf[3]*p0 + g_xf[4]*p1 + g_xf[5]*p2;
    float q2 = g_xf[6]*p0 + g_xf[7]*p1 + g_xf[8]*p2;

    float acc0 = 0.f, acc1 = 0.f, acc2 = 0.f;

    #pragma unroll 1
    for (int n = 0; n < NCAM; n++) {
        const float* X = g_xf + 12 + n*24;
        float c0 = X[0]*q0 + X[1]*q1 + X[2]*q2 + X[9];
        float c1 = X[3]*q0 + X[4]*q1 + X[5]*q2 + X[10];
        float c2 = X[6]*q0 + X[7]*q1 + X[8]*q2 + X[11];
        float z  = fminf(fmaxf(c2, 1e-5f), 1e5f);
        float vx = c0 / z, vy = c1 / z;
        float d0 = X[12]*vx + X[13]*vy + X[14]*z + X[21];
        float d1 = X[15]*vx + X[16]*vy + X[17]*z + X[22];
        float gx = (d0 / 704.0f - 0.5f) * 2.0f;
        float gy = (d1 / 256.0f - 0.5f) * 2.0f;
        float x = (gx + 1.0f) * 0.5f * (float)(W_FEAT - 1);
        float y = (gy + 1.0f) * 0.5f * (float)(H_FEAT - 1);
        float x0f = floorf(x), y0f = floorf(y);
        float wx1 = x - x0f, wy1 = y - y0f;
        float wx0 = 1.0f - wx1, wy0 = 1.0f - wy1;
        bool vx0 = (x0f >= 0.f) && (x0f <= (float)(W_FEAT-1));
        bool vx1 = (x0f+1.f >= 0.f) && (x0f+1.f <= (float)(W_FEAT-1));
        bool vy0 = (y0f >= 0.f) && (y0f <= (float)(H_FEAT-1));
        bool vy1 = (y0f+1.f >= 0.f) && (y0f+1.f <= (float)(H_FEAT-1));
        float w00 = (vx0 && vy0) ? wx0*wy0 : 0.f;
        float w10 = (vx1 && vy0) ? wx1*wy0 : 0.f;
        float w01 = (vx0 && vy1) ? wx0*wy1 : 0.f;
        float w11 = (vx1 && vy1) ? wx1*wy1 : 0.f;
        if (w00 == 0.f && w10 == 0.f && w01 == 0.f && w11 == 0.f) continue;

        int x0i = (int)fminf(fmaxf(x0f,      0.f), (float)(W_FEAT-1));
        int x1i = (int)fminf(fmaxf(x0f+1.f,  0.f), (float)(W_FEAT-1));
        int y0i = (int)fminf(fmaxf(y0f,      0.f), (float)(H_FEAT-1));
        int y1i = (int)fminf(fmaxf(y0f+1.f,  0.f), (float)(H_FEAT-1));

        const float* row0 = g_imgt + ((size_t)(n*H_FEAT + y0i)*W_FEAT)*C_IMG;
        const float* row1 = g_imgt + ((size_t)(n*H_FEAT + y1i)*W_FEAT)*C_IMG;
        const float* p00 = row0 + x0i*C_IMG;
        const float* p10 = row0 + x1i*C_IMG;
        const float* p01 = row1 + x0i*C_IMG;
        const float* p11 = row1 + x1i*C_IMG;

        acc0 += w00*p00[lane]    + w10*p10[lane]    + w01*p01[lane]    + w11*p11[lane];
        acc1 += w00*p00[lane+32] + w10*p10[lane+32] + w01*p01[lane+32] + w11*p11[lane+32];
        acc2 += w00*p00[lane+64] + w10*p10[lane+64] + w01*p01[lane+64] + w11*p11[lane+64];
    }

    float* frow = g_fuse + (size_t)m*FUSE_DIM;
    float4 pv = ((const float4*)(pts + (size_t)m*PTS_DIM))[lane];
    ((float4*)frow)[lane] = pv;
    frow[128 + lane] = acc0;
    frow[160 + lane] = acc1;
    frow[192 + lane] = acc2;
}

// ---------------- build per-offset worklists ----------------
__global__ void k_entries(const int* __restrict__ vc) {
    int m = blockIdx.x*blockDim.x + threadIdx.x;
    bool inb = m < M_PTS;
    int cz = 0, cy = 0, cx = 0;
    if (inb) { cz = vc[4*m+1]; cy = vc[4*m+2]; cx = vc[4*m+3]; }
    int lane = threadIdx.x & 31;
    #pragma unroll 1
    for (int k = 0; k < 27; k++) {
        int dz = k/9 - 1, dy = (k%9)/3 - 1, dx = k%3 - 1;
        int nz = cz + dz, ny = cy + dy, nx = cx + dx;
        int nid = -1;
        if (inb && nz >= 0 && nz < GZ && ny >= 0 && ny < GY && nx >= 0 && nx < GX)
            nid = g_grid[(nz*GY + ny)*GX + nx];
        bool has = nid >= 0;
        unsigned mask = __ballot_sync(0xffffffffu, has);
        if (mask) {
            int leader = __ffs(mask) - 1;
            int base = 0;
            if (lane == leader) base = atomicAdd(&g_cnt[k], __popc(mask));
            base = __shfl_sync(0xffffffffu, base, leader);
            if (has) {
                int pos = base + __popc(mask & ((1u << lane) - 1u));
                g_ents[(size_t)k*M_PTS + pos] = make_int2(m, nid);
            }
        }
    }
}

// ---------------- prefix offsets of tiles for the 26 non-center buckets ----------------
__global__ void k_offsets() {
    if (threadIdx.x != 0 || blockIdx.x != 0) return;
    int s = 0;
    for (int k = 0; k < 27; k++) {
        g_tileoff[k] = s;
        if (k != 13) s += (g_cnt[k] + TILE_E - 1) / TILE_E;
    }
    g_tileoff[27] = s;
}

// ---------------- 128x128 GEMM tile, f32x2 packed FMA ----------------
// STORE=true: plain float4 stores (center tap, covers every output row exactly once)
// STORE=false: atomicAdd accumulate
template<bool STORE>
__device__ __forceinline__ void conv_tile(int k, int tile, const float* __restrict__ conv_w,
                                          int2* se, float (*As)[128], float (*Bs)[128]) {
    int n = g_cnt[k];
    int e0 = tile * TILE_E;

    int tid = threadIdx.x;
    if (tid < TILE_E) {
        int e = e0 + tid;
        se[tid] = (e < n) ? g_ents[(size_t)k*M_PTS + e] : make_int2(-1, -1);
    }
    __syncthreads();

    const float* Wk = conv_w + (size_t)k*FUSE_DIM*PTS_DIM;
    int ty = tid >> 4, tx = tid & 15;         // 16x16 thread grid; 8 rows x 8 cols each
    int arow = tid >> 1, ahalf = tid & 1;     // A loader: row 0..127, half 0/1 (8 floats)
    int aj = se[arow].y;
    const float4* afrow = (const float4*)(g_fuse + (size_t)(aj >= 0 ? aj : 0)*FUSE_DIM);

    ull acc[4][8];
    #pragma unroll
    for (int r = 0; r < 4; r++)
        #pragma unroll
        for (int c = 0; c < 8; c++) acc[r][c] = 0ull;

    for (int k0 = 0; k0 < FUSE_DIM; k0 += 16) {
        float4 a0 = make_float4(0.f,0.f,0.f,0.f), a1 = a0;
        if (aj >= 0) {
            a0 = afrow[(k0 >> 2) + ahalf*2];
            a1 = afrow[(k0 >> 2) + ahalf*2 + 1];
        }
        int kb = ahalf*8;
        As[kb+0][arow] = a0.x; As[kb+1][arow] = a0.y;
        As[kb+2][arow] = a0.z; As[kb+3][arow] = a0.w;
        As[kb+4][arow] = a1.x; As[kb+5][arow] = a1.y;
        As[kb+6][arow] = a1.z; As[kb+7][arow] = a1.w;

        const float4* brow = (const float4*)(Wk + (size_t)(k0 + ty)*PTS_DIM);
        float4 b0v = brow[tx*2], b1v = brow[tx*2 + 1];
        *((float4*)&Bs[ty][tx*8])     = b0v;
        *((float4*)&Bs[ty][tx*8 + 4]) = b1v;
        __syncthreads();

        #pragma unroll
        for (int kk = 0; kk < 16; kk++) {
            // a-pairs come packed for free: rows (2r, 2r+1) adjacent in a 128-bit load
            ulonglong2 aA = *((const ulonglong2*)&As[kk][ty*8]);
            ulonglong2 aB = *((const ulonglong2*)&As[kk][ty*8 + 4]);
            ull a2[4] = { aA.x, aA.y, aB.x, aB.y };
            float4 bb0 = *((const float4*)&Bs[kk][tx*8]);
            float4 bb1 = *((const float4*)&Bs[kk][tx*8 + 4]);
            float bv[8] = { bb0.x, bb0.y, bb0.z, bb0.w, bb1.x, bb1.y, bb1.z, bb1.w };
            #pragma unroll
            for (int c = 0; c < 8; c++) {
                ull b2 = pack2(bv[c]);
                #pragma unroll
                for (int r = 0; r < 4; r++)
                    ffma2(acc[r][c], a2[r], b2);
            }
        }
        __syncthreads();
    }

    #pragma unroll
    for (int rp = 0; rp < 4; rp++) {
        int i0 = se[ty*8 + 2*rp].x;
        int i1 = se[ty*8 + 2*rp + 1].x;
        if (i0 >= 0) {
            float* dst = g_acc + (size_t)i0*PTS_DIM + tx*8;
            if (STORE) {
                float4 v0 = make_float4(lo32(acc[rp][0]), lo32(acc[rp][1]), lo32(acc[rp][2]), lo32(acc[rp][3]));
                float4 v1 = make_float4(lo32(acc[rp][4]), lo32(acc[rp][5]), lo32(acc[rp][6]), lo32(acc[rp][7]));
                ((float4*)dst)[0] = v0;
                ((float4*)dst)[1] = v1;
            } else {
                #pragma unroll
                for (int c = 0; c < 8; c++) atomicAdd(&dst[c], lo32(acc[rp][c]));
            }
        }
        if (i1 >= 0) {
            float* dst = g_acc + (size_t)i1*PTS_DIM + tx*8;
            if (STORE) {
                float4 v0 = make_float4(hi32(acc[rp][0]), hi32(acc[rp][1]), hi32(acc[rp][2]), hi32(acc[rp][3]));
                float4 v1 = make_float4(hi32(acc[rp][4]), hi32(acc[rp][5]), hi32(acc[rp][6]), hi32(acc[rp][7]));
                ((float4*)dst)[0] = v0;
                ((float4*)dst)[1] = v1;
            } else {
                #pragma unroll
                for (int c = 0; c < 8; c++) atomicAdd(&dst[c], hi32(acc[rp][c]));
            }
        }
    }
}

// center tap: k=13, one tile per block, plain stores (covers all rows)
__global__ __launch_bounds__(256) void k_conv_center(const float* __restrict__ conv_w) {
    __shared__ int2  se[TILE_E];
    __shared__ __align__(16) float As[16][128];
    __shared__ __align__(16) float Bs[16][128];
    conv_tile<true>(13, blockIdx.x, conv_w, se, As, Bs);
}

// 26 neighbor taps: grid-stride over real tiles only, atomic accumulate
__global__ __launch_bounds__(256) void k_conv_other(const float* __restrict__ conv_w) {
    __shared__ int   off[28];
    __shared__ int2  se[TILE_E];
    __shared__ __align__(16) float As[16][128];
    __shared__ __align__(16) float Bs[16][128];
    if (threadIdx.x < 28) off[threadIdx.x] = g_tileoff[threadIdx.x];
    __syncthreads();
    int total = off[27];
    for (int w = blockIdx.x; w < total; w += gridDim.x) {
        int k = 0;
        while (w >= off[k+1]) k++;     // off[13]==off[14] -> bucket 13 never selected
        conv_tile<false>(k, w - off[k], conv_w, se, As, Bs);
        __syncthreads();
    }
}

// ---------------- BN + ReLU epilogue ----------------
__global__ void k_bn(const float* __restrict__ gamma, const float* __restrict__ beta,
                     const float* __restrict__ mean,  const float* __restrict__ var,
                     float* __restrict__ out) {
    int i = blockIdx.x*blockDim.x + threadIdx.x;     // over float4 elements
    if (i >= M_PTS*PTS_DIM/4) return;
    int c4 = (i & 31) * 4;
    float4 v = ((const float4*)g_acc)[i];
    float4 o;
    {
        float s = rsqrtf(var[c4+0] + 1e-5f);
        o.x = fmaxf((v.x - mean[c4+0]) * s * gamma[c4+0] + beta[c4+0], 0.f);
    }
    {
        float s = rsqrtf(var[c4+1] + 1e-5f);
        o.y = fmaxf((v.y - mean[c4+1]) * s * gamma[c4+1] + beta[c4+1], 0.f);
    }
    {
        float s = rsqrtf(var[c4+2] + 1e-5f);
        o.z = fmaxf((v.z - mean[c4+2]) * s * gamma[c4+2] + beta[c4+2], 0.f);
    }
    {
        float s = rsqrtf(var[c4+3] + 1e-5f);
        o.w = fmaxf((v.w - mean[c4+3]) * s * gamma[c4+3] + beta[c4+3], 0.f);
    }
    ((float4*)out)[i] = o;
}

extern "C" void kernel_launch(void* const* d_in, const int* in_sizes, int n_in,
                              void* d_out, int out_size) {
    const float* pts   = (const float*)d_in[0];
    const int*   vc    = (const int*)  d_in[1];
    const float* img   = (const float*)d_in[2];
    const float* l2i   = (const float*)d_in[3];
    const float* iaug  = (const float*)d_in[4];
    const float* laug  = (const float*)d_in[5];
    const float* convw = (const float*)d_in[6];
    const float* gamma = (const float*)d_in[7];
    const float* beta  = (const float*)d_in[8];
    const float* mean  = (const float*)d_in[9];
    const float* var   = (const float*)d_in[10];
    float* out = (float*)d_out;

    k_setup<<<1, 32>>>(laug, l2i, iaug);
    {
        const int total = NCAM*C_IMG*H_FEAT*W_FEAT;
        k_transpose<<<(total + 255)/256, 256>>>(img);
    }
    k_init<<<(GRID_N + 255)/256, 256>>>();
    k_scatter<<<(M_PTS + 255)/256, 256>>>(vc);
    k_fuse<<<M_PTS/8, 256>>>(pts, vc);
    k_entries<<<(M_PTS + 255)/256, 256>>>(vc);
    k_offsets<<<1, 32>>>();
    k_conv_center<<<CENTER_TILES, 256>>>(convw);
    k_conv_other<<<2048, 256>>>(convw);
    k_bn<<<(M_PTS*PTS_DIM/4 + 255)/256, 256>>>(gamma, beta, mean, var, out);
}